// round 1
// baseline (speedup 1.0000x reference)
#include <cuda_runtime.h>
#include <cuda_bf16.h>

#define LL 2048
#define BB 64
#define KK 4
#define CC 128
#define II 512
#define NITEMS (II * BB)   // 32768
#define NPERM 24

// global accumulator (no allocations allowed -> __device__ global)
__device__ double g_acc;

// permutations of {0,1,2,3}, packed one byte per position (little-endian)
__constant__ unsigned int c_perms[NPERM] = {
    0x03020100u, 0x02030100u, 0x03010200u, 0x01030200u, 0x02010300u, 0x01020300u,
    0x03020001u, 0x02030001u, 0x03000201u, 0x00030201u, 0x02000301u, 0x00020301u,
    0x03010002u, 0x01030002u, 0x03000102u, 0x00030102u, 0x01000302u, 0x00010302u,
    0x02010003u, 0x01020003u, 0x02000103u, 0x00020103u, 0x01000203u, 0x00010203u
};

__global__ void zero_kernel() { g_acc = 0.0; }

__global__ __launch_bounds__(256) void detpp_main_kernel(
    const float* __restrict__ in_time,     // (L, B)
    const float* __restrict__ in_amount,   // (L, B)
    const int*   __restrict__ in_mcc,      // (L, B)
    const float* __restrict__ out_time,    // (L, B, K)
    const float* __restrict__ out_amount,  // (L, B, K)
    const float* __restrict__ out_logits,  // (L, B, K, C)
    const float* __restrict__ presence,    // (L, B, K)
    const int*   __restrict__ indices,     // (I, B)
    const int*   __restrict__ subset_lengths) // (B,)
{
    __shared__ double s_acc;
    __shared__ unsigned int s_perms[32];

    int tid = threadIdx.x;
    if (tid == 0) s_acc = 0.0;
    if (tid < 32) s_perms[tid] = c_perms[tid < NPERM ? tid : 0];
    __syncthreads();

    int gwarp = (blockIdx.x * blockDim.x + tid) >> 5;
    int lane  = tid & 31;

    if (gwarp < NITEMS) {
        int b = gwarp & (BB - 1);
        int i = gwarp >> 6;   // B = 64

        if (i < subset_lengths[b]) {
            int idx = indices[i * BB + b];
            int row = idx * BB + b;               // (l,b) flat index
            const float* lp = out_logits + (size_t)row * (KK * CC);

            // ---- logsumexp for the 4 logit rows (whole warp, coalesced float4) ----
            float lse[KK];
            #pragma unroll
            for (int k = 0; k < KK; k++) {
                float4 v = *reinterpret_cast<const float4*>(lp + k * CC + lane * 4);
                float mx = fmaxf(fmaxf(v.x, v.y), fmaxf(v.z, v.w));
                #pragma unroll
                for (int o = 16; o; o >>= 1)
                    mx = fmaxf(mx, __shfl_xor_sync(0xffffffffu, mx, o));
                float s = __expf(v.x - mx) + __expf(v.y - mx)
                        + __expf(v.z - mx) + __expf(v.w - mx);
                #pragma unroll
                for (int o = 16; o; o >>= 1)
                    s += __shfl_xor_sync(0xffffffffu, s, o);
                lse[k] = mx + __logf(s);
            }

            // ---- cost matrix: lane = k*4 + t  (lanes 0..15) ----
            int k = lane >> 2;
            int t = lane & 3;
            float cost = 0.f;
            float contrib = 0.f;
            if (lane < 16) {
                float tw0 = in_time[row];
                int r = idx + t + 1;
                if (r >= LL) r -= LL;             // jnp.roll wrap (unreachable for valid items)
                int rrow = r * BB + b;
                float twt = in_time[rrow];
                float awt = in_amount[rrow];
                int   cwt = in_mcc[rrow];

                int obase = row * KK + k;
                float ot = out_time[obase];
                float oa = out_amount[obase];
                float ps = presence[obase];
                float sel = lp[k * CC + cwt];

                cost = lse[k] - sel
                     + fabsf(ot - (twt - tw0))
                     + fabsf(oa - awt)
                     - ps;

                if (t == 0) {
                    // softplus(ps) = -log_sigmoid(-ps), numerically stable
                    contrib = (ps > 0.f) ? ps + __logf(1.f + __expf(-ps))
                                         : __logf(1.f + __expf(ps));
                }
            }

            // ---- exact assignment: min over 24 permutations via shuffles ----
            unsigned int pm = s_perms[lane];
            float pc = 0.f;
            #pragma unroll
            for (int kk = 0; kk < KK; kk++) {
                int src = (kk << 2) + ((pm >> (8 * kk)) & 3);
                pc += __shfl_sync(0xffffffffu, cost, src);
            }
            if (lane >= NPERM) pc = 3.4e38f;
            #pragma unroll
            for (int o = 16; o; o >>= 1)
                pc = fminf(pc, __shfl_xor_sync(0xffffffffu, pc, o));

            if (lane == 0) contrib += pc;

            // ---- warp sum of contrib, then block-local double accumulation ----
            #pragma unroll
            for (int o = 16; o; o >>= 1)
                contrib += __shfl_xor_sync(0xffffffffu, contrib, o);
            if (lane == 0)
                atomicAdd(&s_acc, (double)contrib);
        }
    }

    __syncthreads();
    if (tid == 0)
        atomicAdd(&g_acc, s_acc);
}

__global__ void finalize_kernel(const int* __restrict__ subset_lengths,
                                float* __restrict__ out)
{
    int v = 0;
    #pragma unroll
    for (int b = 0; b < BB; b++) v += subset_lengths[b];
    out[0] = (float)(g_acc / (double)v);
}

extern "C" void kernel_launch(void* const* d_in, const int* in_sizes, int n_in,
                              void* d_out, int out_size)
{
    const float* in_time        = (const float*)d_in[0];
    const float* in_amount      = (const float*)d_in[1];
    const int*   in_mcc         = (const int*)  d_in[2];
    const float* out_time       = (const float*)d_in[3];
    const float* out_amount     = (const float*)d_in[4];
    const float* out_logits     = (const float*)d_in[5];
    const float* presence       = (const float*)d_in[6];
    // d_in[7] = lengths (unused; subset_lengths already encodes validity)
    const int*   indices        = (const int*)  d_in[8];
    const int*   subset_lengths = (const int*)  d_in[9];
    float* out = (float*)d_out;

    zero_kernel<<<1, 1>>>();
    // one warp per item: 32768 warps -> 4096 blocks of 256 threads (8 warps)
    detpp_main_kernel<<<NITEMS / 8, 256>>>(
        in_time, in_amount, in_mcc, out_time, out_amount,
        out_logits, presence, indices, subset_lengths);
    finalize_kernel<<<1, 1>>>(subset_lengths, out);
}